// round 6
// baseline (speedup 1.0000x reference)
#include <cuda_runtime.h>
#include <cuda_bf16.h>
#include <math.h>
#include <stdint.h>

#define BB 8
#define NN 4096
#define DEG 16
#define UU 128
#define EE (NN*DEG)
#define MM (BB*NN)
#define K2 256
#define DEPTH 3
#define SCALE_C 1.2304489f
#define THREADS 512

// ------------------- device scratch (ping-pong feature buffers) -------------------
__device__ float g_xa[(size_t)MM * UU];
__device__ float g_xb[(size_t)MM * UU];
__device__ __nv_bfloat16 g_bhi[DEPTH * UU * K2];       // folded W, [n][k] K-major, hi
__device__ __nv_bfloat16 g_blo[DEPTH * UU * K2];
__device__ float g_bn_a[DEPTH * UU];
__device__ float g_bn_d[DEPTH * UU];
__device__ float g_gm[BB * UU];
__device__ float g_h1[BB * UU];

// ------------------- helpers -------------------
__device__ __forceinline__ uint32_t smem_u32(const void* p) {
    uint32_t a;
    asm("{ .reg .u64 t; cvta.to.shared.u64 t, %1; cvt.u32.u64 %0, t; }" : "=r"(a) : "l"(p));
    return a;
}
__device__ __forceinline__ void cp16(uint32_t dst, const void* src) {
    asm volatile("cp.async.cg.shared.global [%0], [%1], 16;" :: "r"(dst), "l"(src) : "memory");
}
__device__ __forceinline__ void ldmx4(uint32_t* r, uint32_t addr) {
    asm volatile("ldmatrix.sync.aligned.m8n8.x4.shared.b16 {%0,%1,%2,%3}, [%4];"
                 : "=r"(r[0]), "=r"(r[1]), "=r"(r[2]), "=r"(r[3]) : "r"(addr));
}
__device__ __forceinline__ void mma_bf16(float* c, const uint32_t* a, uint32_t b0, uint32_t b1) {
    asm volatile("mma.sync.aligned.m16n8k16.row.col.f32.bf16.bf16.f32 "
                 "{%0,%1,%2,%3}, {%4,%5,%6,%7}, {%8,%9}, {%0,%1,%2,%3};"
                 : "+f"(c[0]), "+f"(c[1]), "+f"(c[2]), "+f"(c[3])
                 : "r"(a[0]), "r"(a[1]), "r"(a[2]), "r"(a[3]), "r"(b0), "r"(b1));
}
#define SWZ(off) ((off) ^ (((off) >> 3) & 0x70))

// ------------------- weight folding (bf16 split, K-major [n][k]) -------------------
__global__ void fold_w_kernel(const float* __restrict__ W) {
    int t = blockIdx.x * blockDim.x + threadIdx.x;
    if (t >= DEPTH * K2 * UU) return;
    int j = t & 127;          // output feature n
    int k = (t >> 7) & 255;   // k index
    int l = t >> 15;
    const float c = SCALE_C;
    const float* Wl = W + (size_t)l * 1152 * UU;
    float v;
    if (k < 128) {
        float w0 = Wl[(0 * 128 + k) * UU + j];
        float w1 = Wl[(1 * 128 + k) * UU + j];
        float w2 = Wl[(2 * 128 + k) * UU + j];
        float w6 = Wl[(6 * 128 + k) * UU + j];
        float w7 = Wl[(7 * 128 + k) * UU + j];
        float w8 = Wl[(8 * 128 + k) * UU + j];
        v = (w0 + c * (w1 + w2)) * 0.0625f + w6 + c * (w7 + w8);
    } else {
        int kk = k - 128;
        float w3 = Wl[(3 * 128 + kk) * UU + j];
        float w4 = Wl[(4 * 128 + kk) * UU + j];
        float w5 = Wl[(5 * 128 + kk) * UU + j];
        v = w3 + c * (w4 + w5);
    }
    __nv_bfloat16 hi = __float2bfloat16_rn(v);
    size_t o = (size_t)l * UU * K2 + (size_t)j * K2 + k;
    g_bhi[o] = hi;
    g_blo[o] = __float2bfloat16_rn(v - __bfloat162float(hi));
}

// also zeroes g_gm for the readout accumulation
__global__ void fold_bn_kernel(const float* __restrict__ gamma, const float* __restrict__ beta,
                               const float* __restrict__ mm, const float* __restrict__ mv) {
    int t = blockIdx.x * blockDim.x + threadIdx.x;
    if (t < BB * UU) g_gm[t] = 0.f;
    if (t >= DEPTH * UU) return;
    float a = gamma[t] * rsqrtf(mv[t] + 1e-3f);
    g_bn_a[t] = a;
    g_bn_d[t] = beta[t] - mm[t] * a;
}

// ------------------- fused layer kernel: agg + bf16-split + GEMM + BN epilogue -------------------
// Per CTA: M=64 nodes, N=128 outputs, K=256 ([ssum|smax]), 512 threads / 16 warps.
#define SB_HI 0
#define SB_LO 65536
#define SA_HI 131072
#define SA_LO (131072 + 32768)
#define S_EPI (131072 + 65536)
#define FUSED_SMEM (S_EPI + 3*128*4)

__global__ __launch_bounds__(THREADS, 1) void fused_layer_kernel(
        int l, const float* __restrict__ xin, float* __restrict__ xout,
        const int* __restrict__ ei, const float* __restrict__ bias) {
    extern __shared__ __align__(1024) char smem[];
    uint32_t sb = smem_u32(smem);
    int tid = threadIdx.x, lane = tid & 31, wid = tid >> 5;

    // ---- stage B (hi+lo = 128KB) via cp.async; overlaps with the gather below ----
    const __nv_bfloat16* Bh = g_bhi + (size_t)l * UU * K2;
    const __nv_bfloat16* Bl = g_blo + (size_t)l * UU * K2;
    #pragma unroll
    for (int t = 0; t < 16; t++) {
        int q = tid + t * THREADS;      // 0..8191
        int arr = q >> 12;              // 0 hi, 1 lo
        int rem = q & 4095;
        int ch = rem >> 10;
        int seg = rem & 1023;           // 128 rows x 8 f16x8-segments
        int row = seg >> 3, s = seg & 7;
        uint32_t dst = sb + (arr ? SB_LO : SB_HI) + ch * 16384 + SWZ((uint32_t)(row * 128 + s * 16));
        const char* src = (const char*)(arr ? Bl : Bh) + (size_t)row * 512 + ch * 128 + s * 16;
        cp16(dst, src);
    }
    asm volatile("cp.async.commit_group;" ::: "memory");

    // ---- epilogue params ----
    float* sepi = (float*)(smem + S_EPI);
    if (tid < 128) {
        sepi[tid]       = __ldg(bias + tid);
        sepi[128 + tid] = g_bn_a[l * UU + tid];
        sepi[256 + tid] = g_bn_d[l * UU + tid];
    }

    // ---- aggregation: each warp handles 4 nodes; lane owns cols 4*lane..4*lane+3 ----
    int node0 = blockIdx.x * 64;
    int b = node0 >> 12;
    int nd0 = node0 & (NN - 1);
    const float* xb = xin + (size_t)b * NN * UU;
    const float ninf = __int_as_float(0xff800000);

    uint32_t csum = (uint32_t)(lane >> 4) * 8192;
    uint32_t cmax = csum + 2 * 8192;
    uint32_t cb   = (uint32_t)(lane & 15) * 8;

    #pragma unroll 1
    for (int i = 0; i < 4; i++) {
        int r = wid * 4 + i;            // local node row 0..63
        const int* ep = ei + 2 * ((size_t)b * EE + (size_t)(nd0 + r) * DEG);
        int myd = (lane < DEG) ? ep[2 * lane + 1] : 0;
        float4 s = make_float4(0.f, 0.f, 0.f, 0.f);
        float4 mx = make_float4(ninf, ninf, ninf, ninf);
        #pragma unroll
        for (int e = 0; e < DEG; e++) {
            int d = __shfl_sync(0xffffffffu, myd, e);
            float4 v = __ldg((const float4*)(xb + (size_t)d * UU + lane * 4));
            s.x += v.x; s.y += v.y; s.z += v.z; s.w += v.w;
            mx.x = fmaxf(mx.x, v.x); mx.y = fmaxf(mx.y, v.y);
            mx.z = fmaxf(mx.z, v.z); mx.w = fmaxf(mx.w, v.w);
        }
        float sv[4] = {s.x, s.y, s.z, s.w};
        float mv[4] = {mx.x, mx.y, mx.z, mx.w};
        uint32_t sh[4], sl[4], mh[4], ml[4];
        #pragma unroll
        for (int q = 0; q < 4; q++) {
            __nv_bfloat16 h1 = __float2bfloat16_rn(sv[q]);
            sh[q] = (uint32_t)__bfloat16_as_ushort(h1);
            sl[q] = (uint32_t)__bfloat16_as_ushort(__float2bfloat16_rn(sv[q] - __bfloat162float(h1)));
            __nv_bfloat16 h2 = __float2bfloat16_rn(mv[q]);
            mh[q] = (uint32_t)__bfloat16_as_ushort(h2);
            ml[q] = (uint32_t)__bfloat16_as_ushort(__float2bfloat16_rn(mv[q] - __bfloat162float(h2)));
        }
        uint32_t rowoff = (uint32_t)(r * 128) + (cb ^ (uint32_t)((r & 7) << 4));
        uint2 u;
        u.x = sh[0] | (sh[1] << 16); u.y = sh[2] | (sh[3] << 16);
        *(uint2*)(smem + SA_HI + csum + rowoff) = u;
        u.x = sl[0] | (sl[1] << 16); u.y = sl[2] | (sl[3] << 16);
        *(uint2*)(smem + SA_LO + csum + rowoff) = u;
        u.x = mh[0] | (mh[1] << 16); u.y = mh[2] | (mh[3] << 16);
        *(uint2*)(smem + SA_HI + cmax + rowoff) = u;
        u.x = ml[0] | (ml[1] << 16); u.y = ml[2] | (ml[3] << 16);
        *(uint2*)(smem + SA_LO + cmax + rowoff) = u;
    }

    asm volatile("cp.async.wait_group 0;" ::: "memory");
    __syncthreads();

    // ---- MMA: 16 warps; warp tile 16 rows x 32 cols; warp_m in {0..3}, warp_n in {0..3} ----
    int warp_m = wid & 3, warp_n = wid >> 2;

    int lrA = lane & 15;
    uint32_t kaA = (uint32_t)((lane >> 4) * 16);
    int rA = warp_m * 16 + lrA;
    uint32_t a_off = (uint32_t)(rA * 128);
    uint32_t a_xor = (a_off >> 3) & 0x70;

    int lnB = (lane & 7) + ((lane >> 4) << 3);
    uint32_t kaB = (uint32_t)(((lane >> 3) & 1) * 16);
    uint32_t b_off[2], b_xor[2];
    #pragma unroll
    for (int p = 0; p < 2; p++) {
        int n = warp_n * 32 + p * 16 + lnB;
        b_off[p] = (uint32_t)(n * 128);
        b_xor[p] = (b_off[p] >> 3) & 0x70;
    }

    float acc[4][4];
    #pragma unroll
    for (int j = 0; j < 4; j++)
        #pragma unroll
        for (int q = 0; q < 4; q++) acc[j][q] = 0.f;

    #pragma unroll
    for (int ch = 0; ch < 4; ch++) {
        uint32_t Ah  = sb + SA_HI + ch * 8192;
        uint32_t Al  = sb + SA_LO + ch * 8192;
        uint32_t Bhs = sb + SB_HI + ch * 16384;
        uint32_t Bls = sb + SB_LO + ch * 16384;
        #pragma unroll
        for (int ks = 0; ks < 4; ks++) {
            uint32_t kb = (uint32_t)(ks * 32);
            uint32_t ahi[4], alo[4], bhi[2][4], blo[2][4];
            ldmx4(ahi, Ah + a_off + ((kb + kaA) ^ a_xor));
            ldmx4(alo, Al + a_off + ((kb + kaA) ^ a_xor));
            #pragma unroll
            for (int p = 0; p < 2; p++) {
                ldmx4(bhi[p], Bhs + b_off[p] + ((kb + kaB) ^ b_xor[p]));
                ldmx4(blo[p], Bls + b_off[p] + ((kb + kaB) ^ b_xor[p]));
            }
            #pragma unroll
            for (int j = 0; j < 4; j++) {
                int p = j >> 1, s2 = (j & 1) * 2;
                mma_bf16(acc[j], ahi, bhi[p][s2], bhi[p][s2 + 1]);
                mma_bf16(acc[j], ahi, blo[p][s2], blo[p][s2 + 1]);
                mma_bf16(acc[j], alo, bhi[p][s2], bhi[p][s2 + 1]);
            }
        }
    }

    // ---- epilogue ----
    int mbase = node0 + warp_m * 16 + (lane >> 2);
    #pragma unroll
    for (int j = 0; j < 4; j++) {
        int col = warp_n * 32 + j * 8 + (lane & 3) * 2;
        float b0 = sepi[col], b1 = sepi[col + 1];
        float a0 = sepi[128 + col], a1 = sepi[128 + col + 1];
        float d0 = sepi[256 + col], d1 = sepi[256 + col + 1];
        float2 o;
        o.x = fmaxf(acc[j][0] + b0, 0.f) * a0 + d0;
        o.y = fmaxf(acc[j][1] + b1, 0.f) * a1 + d1;
        *(float2*)&xout[(size_t)mbase * UU + col] = o;
        o.x = fmaxf(acc[j][2] + b0, 0.f) * a0 + d0;
        o.y = fmaxf(acc[j][3] + b1, 0.f) * a1 + d1;
        *(float2*)&xout[(size_t)(mbase + 8) * UU + col] = o;
    }
}

// ------------------- readout (parallel partial sums + atomicAdd) -------------------
__global__ void readout_kernel(const float* __restrict__ xin) {
    int b = blockIdx.x >> 4;
    int chunk = blockIdx.x & 15;
    int j = threadIdx.x;
    const float* xb = xin + (size_t)b * NN * UU + (size_t)chunk * 256 * UU;
    float s0 = 0.f, s1 = 0.f, s2 = 0.f, s3 = 0.f;
    for (int n = 0; n < 256; n += 4) {
        s0 += xb[(size_t)n * UU + j];
        s1 += xb[(size_t)(n + 1) * UU + j];
        s2 += xb[(size_t)(n + 2) * UU + j];
        s3 += xb[(size_t)(n + 3) * UU + j];
    }
    atomicAdd(&g_gm[b * UU + j], (s0 + s1 + s2 + s3) * (1.f / NN));
}

__global__ void mlp1_kernel(const float* __restrict__ Wp1, const float* __restrict__ bp1) {
    __shared__ float gs[UU];
    int b = blockIdx.x, j = threadIdx.x;
    gs[j] = g_gm[b * UU + j];
    __syncthreads();
    float acc = bp1[j];
    #pragma unroll 8
    for (int k = 0; k < UU; k++) acc += gs[k] * Wp1[k * UU + j];
    g_h1[b * UU + j] = fmaxf(acc, 0.f);
}

__global__ void mlp2_kernel(const float* __restrict__ Wp2, const float* __restrict__ bp2,
                            float* __restrict__ out) {
    __shared__ float gs[UU];
    int b = blockIdx.x, j = threadIdx.x;  // 64 threads
    gs[j] = g_h1[b * UU + j];
    gs[j + 64] = g_h1[b * UU + j + 64];
    __syncthreads();
    float acc = bp2[j];
    #pragma unroll 8
    for (int k = 0; k < UU; k++) acc += gs[k] * Wp2[k * 64 + j];
    out[b * 64 + j] = fmaxf(acc, 0.f);
}

// ------------------- launch -------------------
extern "C" void kernel_launch(void* const* d_in, const int* in_sizes, int n_in,
                              void* d_out, int out_size) {
    const float* x0    = (const float*)d_in[0];
    const int*   ei    = (const int*)d_in[1];
    const float* W     = (const float*)d_in[2];
    const float* bvec  = (const float*)d_in[3];
    const float* gamma = (const float*)d_in[4];
    const float* beta  = (const float*)d_in[5];
    const float* mmean = (const float*)d_in[6];
    const float* mvar  = (const float*)d_in[7];
    const float* Wp1   = (const float*)d_in[8];
    const float* bp1   = (const float*)d_in[9];
    const float* Wp2   = (const float*)d_in[10];
    const float* bp2   = (const float*)d_in[11];

    cudaFuncSetAttribute(fused_layer_kernel, cudaFuncAttributeMaxDynamicSharedMemorySize, FUSED_SMEM);

    fold_w_kernel<<<96, 1024>>>(W);
    fold_bn_kernel<<<3, 1024>>>(gamma, beta, mmean, mvar);

    float *xa, *xb;
    cudaGetSymbolAddress((void**)&xa, g_xa);
    cudaGetSymbolAddress((void**)&xb, g_xb);

    // l0: x0 -> xa,  l1: xa -> xb,  l2: xb -> xa
    fused_layer_kernel<<<MM / 64, THREADS, FUSED_SMEM>>>(0, x0, xa, ei, bvec + 0 * UU);
    fused_layer_kernel<<<MM / 64, THREADS, FUSED_SMEM>>>(1, xa, xb, ei, bvec + 1 * UU);
    fused_layer_kernel<<<MM / 64, THREADS, FUSED_SMEM>>>(2, xb, xa, ei, bvec + 2 * UU);

    readout_kernel<<<BB * 16, 128>>>(xa);
    mlp1_kernel<<<BB, 128>>>(Wp1, bp1);
    mlp2_kernel<<<BB, 64>>>(Wp2, bp2, (float*)d_out);
}

// round 7
// speedup vs baseline: 1.5227x; 1.5227x over previous
#include <cuda_runtime.h>
#include <cuda_bf16.h>
#include <math.h>
#include <stdint.h>

#define BB 8
#define NN 4096
#define DEG 16
#define UU 128
#define EE (NN*DEG)
#define MM (BB*NN)
#define K2 256
#define DEPTH 3
#define SCALE_C 1.2304489f
#define NTILES (MM/64)
#define GRIDSZ 148

// ------------------- device scratch (ping-pong feature buffers) -------------------
__device__ float g_xa[(size_t)MM * UU];
__device__ float g_xb[(size_t)MM * UU];
__device__ __nv_bfloat16 g_bhi[DEPTH * UU * K2];       // folded W, [n][k] K-major, hi
__device__ __nv_bfloat16 g_blo[DEPTH * UU * K2];
__device__ float g_bn_a[DEPTH * UU];
__device__ float g_bn_d[DEPTH * UU];
__device__ float g_gm[BB * UU];
__device__ float g_h1[BB * UU];

// ------------------- helpers -------------------
__device__ __forceinline__ uint32_t smem_u32(const void* p) {
    uint32_t a;
    asm("{ .reg .u64 t; cvta.to.shared.u64 t, %1; cvt.u32.u64 %0, t; }" : "=r"(a) : "l"(p));
    return a;
}
__device__ __forceinline__ void cp16(uint32_t dst, const void* src) {
    asm volatile("cp.async.cg.shared.global [%0], [%1], 16;" :: "r"(dst), "l"(src) : "memory");
}
__device__ __forceinline__ void ldmx4(uint32_t* r, uint32_t addr) {
    asm volatile("ldmatrix.sync.aligned.m8n8.x4.shared.b16 {%0,%1,%2,%3}, [%4];"
                 : "=r"(r[0]), "=r"(r[1]), "=r"(r[2]), "=r"(r[3]) : "r"(addr));
}
__device__ __forceinline__ void mma_bf16(float* c, const uint32_t* a, uint32_t b0, uint32_t b1) {
    asm volatile("mma.sync.aligned.m16n8k16.row.col.f32.bf16.bf16.f32 "
                 "{%0,%1,%2,%3}, {%4,%5,%6,%7}, {%8,%9}, {%0,%1,%2,%3};"
                 : "+f"(c[0]), "+f"(c[1]), "+f"(c[2]), "+f"(c[3])
                 : "r"(a[0]), "r"(a[1]), "r"(a[2]), "r"(a[3]), "r"(b0), "r"(b1));
}
#define SWZ(off) ((off) ^ (((off) >> 3) & 0x70))

// ------------------- weight folding (bf16 split, K-major [n][k]) -------------------
__global__ void fold_w_kernel(const float* __restrict__ W) {
    int t = blockIdx.x * blockDim.x + threadIdx.x;
    if (t >= DEPTH * K2 * UU) return;
    int j = t & 127;          // output feature n
    int k = (t >> 7) & 255;   // k index
    int l = t >> 15;
    const float c = SCALE_C;
    const float* Wl = W + (size_t)l * 1152 * UU;
    float v;
    if (k < 128) {
        float w0 = Wl[(0 * 128 + k) * UU + j];
        float w1 = Wl[(1 * 128 + k) * UU + j];
        float w2 = Wl[(2 * 128 + k) * UU + j];
        float w6 = Wl[(6 * 128 + k) * UU + j];
        float w7 = Wl[(7 * 128 + k) * UU + j];
        float w8 = Wl[(8 * 128 + k) * UU + j];
        v = (w0 + c * (w1 + w2)) * 0.0625f + w6 + c * (w7 + w8);
    } else {
        int kk = k - 128;
        float w3 = Wl[(3 * 128 + kk) * UU + j];
        float w4 = Wl[(4 * 128 + kk) * UU + j];
        float w5 = Wl[(5 * 128 + kk) * UU + j];
        v = w3 + c * (w4 + w5);
    }
    __nv_bfloat16 hi = __float2bfloat16_rn(v);
    size_t o = (size_t)l * UU * K2 + (size_t)j * K2 + k;
    g_bhi[o] = hi;
    g_blo[o] = __float2bfloat16_rn(v - __bfloat162float(hi));
}

// also zeroes g_gm for the readout accumulation
__global__ void fold_bn_kernel(const float* __restrict__ gamma, const float* __restrict__ beta,
                               const float* __restrict__ mm, const float* __restrict__ mv) {
    int t = blockIdx.x * blockDim.x + threadIdx.x;
    if (t < BB * UU) g_gm[t] = 0.f;
    if (t >= DEPTH * UU) return;
    float a = gamma[t] * rsqrtf(mv[t] + 1e-3f);
    g_bn_a[t] = a;
    g_bn_d[t] = beta[t] - mm[t] * a;
}

// ------------------- fused persistent layer kernel -------------------
// Per tile: M=64 nodes, N=128, K=256. 256 threads / 8 warps. B staged once per CTA.
#define SB_HI 0
#define SB_LO 65536
#define SA_HI 131072
#define SA_LO (131072 + 32768)
#define S_EPI (131072 + 65536)
#define FUSED_SMEM (S_EPI + 3*128*4)

__global__ __launch_bounds__(256, 1) void fused_layer_kernel(
        int l, const float* __restrict__ xin, float* __restrict__ xout,
        const int* __restrict__ ei, const float* __restrict__ bias) {
    extern __shared__ __align__(1024) char smem[];
    uint32_t sb = smem_u32(smem);
    int tid = threadIdx.x, lane = tid & 31, wid = tid >> 5;

    // ---- stage B (hi+lo = 128KB) once; overlaps first gather ----
    const __nv_bfloat16* Bh = g_bhi + (size_t)l * UU * K2;
    const __nv_bfloat16* Bl = g_blo + (size_t)l * UU * K2;
    #pragma unroll
    for (int t = 0; t < 32; t++) {
        int q = tid + t * 256;          // 0..8191
        int arr = q >> 12;              // 0 hi, 1 lo
        int rem = q & 4095;
        int ch = rem >> 10;
        int seg = rem & 1023;
        int row = seg >> 3, s = seg & 7;
        uint32_t dst = sb + (arr ? SB_LO : SB_HI) + ch * 16384 + SWZ((uint32_t)(row * 128 + s * 16));
        const char* src = (const char*)(arr ? Bl : Bh) + (size_t)row * 512 + ch * 128 + s * 16;
        cp16(dst, src);
    }
    asm volatile("cp.async.commit_group;" ::: "memory");

    // ---- epilogue params ----
    float* sepi = (float*)(smem + S_EPI);
    if (tid < 128) {
        sepi[tid]       = __ldg(bias + tid);
        sepi[128 + tid] = g_bn_a[l * UU + tid];
        sepi[256 + tid] = g_bn_d[l * UU + tid];
    }

    const float ninf = __int_as_float(0xff800000);
    uint32_t csum = (uint32_t)(lane >> 4) * 8192;
    uint32_t cmax = csum + 2 * 8192;
    uint32_t cb   = (uint32_t)(lane & 15) * 8;

    // ---- MMA lane constants ----
    int warp_m = wid & 1, warp_n = wid >> 1;
    int lrA = lane & 15;
    uint32_t kaA = (uint32_t)((lane >> 4) * 16);
    uint32_t a_off[2], a_xor[2];
    #pragma unroll
    for (int i = 0; i < 2; i++) {
        int r = warp_m * 32 + i * 16 + lrA;
        a_off[i] = (uint32_t)(r * 128);
        a_xor[i] = (a_off[i] >> 3) & 0x70;
    }
    int lnB = (lane & 7) + ((lane >> 4) << 3);
    uint32_t kaB = (uint32_t)(((lane >> 3) & 1) * 16);
    uint32_t b_off[2], b_xor[2];
    #pragma unroll
    for (int p = 0; p < 2; p++) {
        int n = warp_n * 32 + p * 16 + lnB;
        b_off[p] = (uint32_t)(n * 128);
        b_xor[p] = (b_off[p] >> 3) & 0x70;
    }

    // ================= persistent tile loop =================
    for (int tile = blockIdx.x; tile < NTILES; tile += GRIDSZ) {
        int node0 = tile * 64;
        int b = node0 >> 12;
        int nd0 = node0 & (NN - 1);
        const float* xb = xin + (size_t)b * NN * UU;

        // ---- gather: each warp handles 8 nodes, 2 interleaved at a time ----
        #pragma unroll 1
        for (int i = 0; i < 4; i++) {
            int r0 = wid * 8 + i * 2;       // local rows r0, r0+1
            const int* ep0 = ei + 2 * ((size_t)b * EE + (size_t)(nd0 + r0) * DEG);
            const int* ep1 = ep0 + 2 * DEG;
            int myd0 = (lane < DEG) ? ep0[2 * lane + 1] : 0;
            int myd1 = (lane < DEG) ? ep1[2 * lane + 1] : 0;
            float4 s0 = make_float4(0.f, 0.f, 0.f, 0.f);
            float4 s1 = make_float4(0.f, 0.f, 0.f, 0.f);
            float4 m0 = make_float4(ninf, ninf, ninf, ninf);
            float4 m1 = make_float4(ninf, ninf, ninf, ninf);
            #pragma unroll
            for (int e = 0; e < DEG; e++) {
                int d0 = __shfl_sync(0xffffffffu, myd0, e);
                int d1 = __shfl_sync(0xffffffffu, myd1, e);
                float4 v0 = __ldg((const float4*)(xb + (size_t)d0 * UU + lane * 4));
                float4 v1 = __ldg((const float4*)(xb + (size_t)d1 * UU + lane * 4));
                s0.x += v0.x; s0.y += v0.y; s0.z += v0.z; s0.w += v0.w;
                m0.x = fmaxf(m0.x, v0.x); m0.y = fmaxf(m0.y, v0.y);
                m0.z = fmaxf(m0.z, v0.z); m0.w = fmaxf(m0.w, v0.w);
                s1.x += v1.x; s1.y += v1.y; s1.z += v1.z; s1.w += v1.w;
                m1.x = fmaxf(m1.x, v1.x); m1.y = fmaxf(m1.y, v1.y);
                m1.z = fmaxf(m1.z, v1.z); m1.w = fmaxf(m1.w, v1.w);
            }
            #pragma unroll
            for (int n2 = 0; n2 < 2; n2++) {
                int r = r0 + n2;
                float sv[4], mv[4];
                if (n2 == 0) { sv[0]=s0.x; sv[1]=s0.y; sv[2]=s0.z; sv[3]=s0.w;
                               mv[0]=m0.x; mv[1]=m0.y; mv[2]=m0.z; mv[3]=m0.w; }
                else         { sv[0]=s1.x; sv[1]=s1.y; sv[2]=s1.z; sv[3]=s1.w;
                               mv[0]=m1.x; mv[1]=m1.y; mv[2]=m1.z; mv[3]=m1.w; }
                uint32_t sh[4], sl[4], mh[4], ml[4];
                #pragma unroll
                for (int q = 0; q < 4; q++) {
                    __nv_bfloat16 h1 = __float2bfloat16_rn(sv[q]);
                    sh[q] = (uint32_t)__bfloat16_as_ushort(h1);
                    sl[q] = (uint32_t)__bfloat16_as_ushort(__float2bfloat16_rn(sv[q] - __bfloat162float(h1)));
                    __nv_bfloat16 h2 = __float2bfloat16_rn(mv[q]);
                    mh[q] = (uint32_t)__bfloat16_as_ushort(h2);
                    ml[q] = (uint32_t)__bfloat16_as_ushort(__float2bfloat16_rn(mv[q] - __bfloat162float(h2)));
                }
                uint32_t rowoff = (uint32_t)(r * 128) + (cb ^ (uint32_t)((r & 7) << 4));
                uint2 u;
                u.x = sh[0] | (sh[1] << 16); u.y = sh[2] | (sh[3] << 16);
                *(uint2*)(smem + SA_HI + csum + rowoff) = u;
                u.x = sl[0] | (sl[1] << 16); u.y = sl[2] | (sl[3] << 16);
                *(uint2*)(smem + SA_LO + csum + rowoff) = u;
                u.x = mh[0] | (mh[1] << 16); u.y = mh[2] | (mh[3] << 16);
                *(uint2*)(smem + SA_HI + cmax + rowoff) = u;
                u.x = ml[0] | (ml[1] << 16); u.y = ml[2] | (ml[3] << 16);
                *(uint2*)(smem + SA_LO + cmax + rowoff) = u;
            }
        }

        asm volatile("cp.async.wait_group 0;" ::: "memory");
        __syncthreads();

        // ---- MMA ----
        float acc[2][4][4];
        #pragma unroll
        for (int i = 0; i < 2; i++)
            #pragma unroll
            for (int j = 0; j < 4; j++)
                #pragma unroll
                for (int q = 0; q < 4; q++) acc[i][j][q] = 0.f;

        #pragma unroll
        for (int ch = 0; ch < 4; ch++) {
            uint32_t Ah  = sb + SA_HI + ch * 8192;
            uint32_t Al  = sb + SA_LO + ch * 8192;
            uint32_t Bhs = sb + SB_HI + ch * 16384;
            uint32_t Bls = sb + SB_LO + ch * 16384;
            #pragma unroll
            for (int ks = 0; ks < 4; ks++) {
                uint32_t kb = (uint32_t)(ks * 32);
                uint32_t ahi[2][4], alo[2][4], bhi[2][4], blo[2][4];
                #pragma unroll
                for (int i = 0; i < 2; i++) {
                    ldmx4(ahi[i], Ah + a_off[i] + ((kb + kaA) ^ a_xor[i]));
                    ldmx4(alo[i], Al + a_off[i] + ((kb + kaA) ^ a_xor[i]));
                }
                #pragma unroll
                for (int p = 0; p < 2; p++) {
                    ldmx4(bhi[p], Bhs + b_off[p] + ((kb + kaB) ^ b_xor[p]));
                    ldmx4(blo[p], Bls + b_off[p] + ((kb + kaB) ^ b_xor[p]));
                }
                #pragma unroll
                for (int i = 0; i < 2; i++)
                    #pragma unroll
                    for (int j = 0; j < 4; j++) {
                        int p = j >> 1, s2 = (j & 1) * 2;
                        mma_bf16(acc[i][j], ahi[i], bhi[p][s2], bhi[p][s2 + 1]);
                        mma_bf16(acc[i][j], ahi[i], blo[p][s2], blo[p][s2 + 1]);
                        mma_bf16(acc[i][j], alo[i], bhi[p][s2], bhi[p][s2 + 1]);
                    }
            }
        }

        // ---- epilogue ----
        int mbase = node0 + warp_m * 32 + (lane >> 2);
        #pragma unroll
        for (int i = 0; i < 2; i++)
            #pragma unroll
            for (int j = 0; j < 4; j++) {
                int col = warp_n * 32 + j * 8 + (lane & 3) * 2;
                float b0 = sepi[col], b1 = sepi[col + 1];
                float a0 = sepi[128 + col], a1 = sepi[128 + col + 1];
                float d0 = sepi[256 + col], d1 = sepi[256 + col + 1];
                int r0 = mbase + i * 16;
                float2 o;
                o.x = fmaxf(acc[i][j][0] + b0, 0.f) * a0 + d0;
                o.y = fmaxf(acc[i][j][1] + b1, 0.f) * a1 + d1;
                *(float2*)&xout[(size_t)r0 * UU + col] = o;
                o.x = fmaxf(acc[i][j][2] + b0, 0.f) * a0 + d0;
                o.y = fmaxf(acc[i][j][3] + b1, 0.f) * a1 + d1;
                *(float2*)&xout[(size_t)(r0 + 8) * UU + col] = o;
            }
        __syncthreads();   // protect A smem reuse by next tile's gather
    }
}

// ------------------- readout (parallel partial sums + atomicAdd) -------------------
__global__ void readout_kernel(const float* __restrict__ xin) {
    int b = blockIdx.x >> 4;
    int chunk = blockIdx.x & 15;
    int j = threadIdx.x;
    const float* xb = xin + (size_t)b * NN * UU + (size_t)chunk * 256 * UU;
    float s0 = 0.f, s1 = 0.f, s2 = 0.f, s3 = 0.f;
    for (int n = 0; n < 256; n += 4) {
        s0 += xb[(size_t)n * UU + j];
        s1 += xb[(size_t)(n + 1) * UU + j];
        s2 += xb[(size_t)(n + 2) * UU + j];
        s3 += xb[(size_t)(n + 3) * UU + j];
    }
    atomicAdd(&g_gm[b * UU + j], (s0 + s1 + s2 + s3) * (1.f / NN));
}

__global__ void mlp1_kernel(const float* __restrict__ Wp1, const float* __restrict__ bp1) {
    __shared__ float gs[UU];
    int b = blockIdx.x, j = threadIdx.x;
    gs[j] = g_gm[b * UU + j];
    __syncthreads();
    float acc = bp1[j];
    #pragma unroll 8
    for (int k = 0; k < UU; k++) acc += gs[k] * Wp1[k * UU + j];
    g_h1[b * UU + j] = fmaxf(acc, 0.f);
}

__global__ void mlp2_kernel(const float* __restrict__ Wp2, const float* __restrict__ bp2,
                            float* __restrict__ out) {
    __shared__ float gs[UU];
    int b = blockIdx.x, j = threadIdx.x;  // 64 threads
    gs[j] = g_h1[b * UU + j];
    gs[j + 64] = g_h1[b * UU + j + 64];
    __syncthreads();
    float acc = bp2[j];
    #pragma unroll 8
    for (int k = 0; k < UU; k++) acc += gs[k] * Wp2[k * 64 + j];
    out[b * 64 + j] = fmaxf(acc, 0.f);
}

// ------------------- launch -------------------
extern "C" void kernel_launch(void* const* d_in, const int* in_sizes, int n_in,
                              void* d_out, int out_size) {
    const float* x0    = (const float*)d_in[0];
    const int*   ei    = (const int*)d_in[1];
    const float* W     = (const float*)d_in[2];
    const float* bvec  = (const float*)d_in[3];
    const float* gamma = (const float*)d_in[4];
    const float* beta  = (const float*)d_in[5];
    const float* mmean = (const float*)d_in[6];
    const float* mvar  = (const float*)d_in[7];
    const float* Wp1   = (const float*)d_in[8];
    const float* bp1   = (const float*)d_in[9];
    const float* Wp2   = (const float*)d_in[10];
    const float* bp2   = (const float*)d_in[11];

    cudaFuncSetAttribute(fused_layer_kernel, cudaFuncAttributeMaxDynamicSharedMemorySize, FUSED_SMEM);

    fold_w_kernel<<<96, 1024>>>(W);
    fold_bn_kernel<<<3, 1024>>>(gamma, beta, mmean, mvar);

    float *xa, *xb;
    cudaGetSymbolAddress((void**)&xa, g_xa);
    cudaGetSymbolAddress((void**)&xb, g_xb);

    // l0: x0 -> xa,  l1: xa -> xb,  l2: xb -> xa
    fused_layer_kernel<<<GRIDSZ, 256, FUSED_SMEM>>>(0, x0, xa, ei, bvec + 0 * UU);
    fused_layer_kernel<<<GRIDSZ, 256, FUSED_SMEM>>>(1, xa, xb, ei, bvec + 1 * UU);
    fused_layer_kernel<<<GRIDSZ, 256, FUSED_SMEM>>>(2, xb, xa, ei, bvec + 2 * UU);

    readout_kernel<<<BB * 16, 128>>>(xa);
    mlp1_kernel<<<BB, 128>>>(Wp1, bp1);
    mlp2_kernel<<<BB, 64>>>(Wp2, bp2, (float*)d_out);
}

// round 8
// speedup vs baseline: 1.8610x; 1.2222x over previous
#include <cuda_runtime.h>
#include <cuda_bf16.h>
#include <math.h>
#include <stdint.h>

#define BB 8
#define NN 4096
#define DEG 16
#define UU 128
#define EE (NN*DEG)
#define MM (BB*NN)
#define K2 256
#define DEPTH 3
#define SCALE_C 1.2304489f
#define THREADS 512
#define TILE_M 32
#define NTILES (MM/TILE_M)
#define GRIDSZ 148

// ------------------- device scratch (ping-pong feature buffers) -------------------
__device__ float g_xa[(size_t)MM * UU];
__device__ float g_xb[(size_t)MM * UU];
__device__ __nv_bfloat16 g_bhi[DEPTH * UU * K2];       // folded W, [n][k] K-major, hi
__device__ __nv_bfloat16 g_blo[DEPTH * UU * K2];
__device__ float g_bn_a[DEPTH * UU];
__device__ float g_bn_d[DEPTH * UU];
__device__ float g_gm[BB * UU];
__device__ float g_h1[BB * UU];

// ------------------- helpers -------------------
__device__ __forceinline__ uint32_t smem_u32(const void* p) {
    uint32_t a;
    asm("{ .reg .u64 t; cvta.to.shared.u64 t, %1; cvt.u32.u64 %0, t; }" : "=r"(a) : "l"(p));
    return a;
}
__device__ __forceinline__ void cp16(uint32_t dst, const void* src) {
    asm volatile("cp.async.cg.shared.global [%0], [%1], 16;" :: "r"(dst), "l"(src) : "memory");
}
__device__ __forceinline__ void ldmx4(uint32_t* r, uint32_t addr) {
    asm volatile("ldmatrix.sync.aligned.m8n8.x4.shared.b16 {%0,%1,%2,%3}, [%4];"
                 : "=r"(r[0]), "=r"(r[1]), "=r"(r[2]), "=r"(r[3]) : "r"(addr));
}
__device__ __forceinline__ void mma_bf16(float* c, const uint32_t* a, uint32_t b0, uint32_t b1) {
    asm volatile("mma.sync.aligned.m16n8k16.row.col.f32.bf16.bf16.f32 "
                 "{%0,%1,%2,%3}, {%4,%5,%6,%7}, {%8,%9}, {%0,%1,%2,%3};"
                 : "+f"(c[0]), "+f"(c[1]), "+f"(c[2]), "+f"(c[3])
                 : "r"(a[0]), "r"(a[1]), "r"(a[2]), "r"(a[3]), "r"(b0), "r"(b1));
}
#define SWZ(off) ((off) ^ (((off) >> 3) & 0x70))
#define BAR_SYNC(id, cnt)   asm volatile("bar.sync %0, %1;"   :: "r"(id), "r"(cnt) : "memory")
#define BAR_ARRIVE(id, cnt) asm volatile("bar.arrive %0, %1;" :: "r"(id), "r"(cnt) : "memory")

// ------------------- weight folding (bf16 split, K-major [n][k]) -------------------
__global__ void fold_w_kernel(const float* __restrict__ W) {
    int t = blockIdx.x * blockDim.x + threadIdx.x;
    if (t >= DEPTH * K2 * UU) return;
    int j = t & 127;          // output feature n
    int k = (t >> 7) & 255;   // k index
    int l = t >> 15;
    const float c = SCALE_C;
    const float* Wl = W + (size_t)l * 1152 * UU;
    float v;
    if (k < 128) {
        float w0 = Wl[(0 * 128 + k) * UU + j];
        float w1 = Wl[(1 * 128 + k) * UU + j];
        float w2 = Wl[(2 * 128 + k) * UU + j];
        float w6 = Wl[(6 * 128 + k) * UU + j];
        float w7 = Wl[(7 * 128 + k) * UU + j];
        float w8 = Wl[(8 * 128 + k) * UU + j];
        v = (w0 + c * (w1 + w2)) * 0.0625f + w6 + c * (w7 + w8);
    } else {
        int kk = k - 128;
        float w3 = Wl[(3 * 128 + kk) * UU + j];
        float w4 = Wl[(4 * 128 + kk) * UU + j];
        float w5 = Wl[(5 * 128 + kk) * UU + j];
        v = w3 + c * (w4 + w5);
    }
    __nv_bfloat16 hi = __float2bfloat16_rn(v);
    size_t o = (size_t)l * UU * K2 + (size_t)j * K2 + k;
    g_bhi[o] = hi;
    g_blo[o] = __float2bfloat16_rn(v - __bfloat162float(hi));
}

// also zeroes g_gm for the readout accumulation
__global__ void fold_bn_kernel(const float* __restrict__ gamma, const float* __restrict__ beta,
                               const float* __restrict__ mm, const float* __restrict__ mv) {
    int t = blockIdx.x * blockDim.x + threadIdx.x;
    if (t < BB * UU) g_gm[t] = 0.f;
    if (t >= DEPTH * UU) return;
    float a = gamma[t] * rsqrtf(mv[t] + 1e-3f);
    g_bn_a[t] = a;
    g_bn_d[t] = beta[t] - mm[t] * a;
}

// ------------------- warp-specialized fused layer kernel -------------------
// 512 threads: warps 0-7 produce (gather->A smem), warps 8-15 consume (MMA+epilogue).
// Tile M=32, N=128, K=256. A double-buffered (2x32KB), B resident (128KB).
#define SB_HI   0
#define SB_LO   65536
#define SA_BASE 131072
#define SA_BUFSZ 32768
#define S_EPI   (131072 + 65536)
#define FUSED_SMEM (S_EPI + 3*128*4)
// named barriers: full[buf]=1+buf, empty[buf]=3+buf, consumer-init=5

__global__ __launch_bounds__(THREADS, 1) void fused_layer_kernel(
        int l, const float* __restrict__ xin, float* __restrict__ xout,
        const int* __restrict__ ei, const float* __restrict__ bias) {
    extern __shared__ __align__(1024) char smem[];
    uint32_t sb = smem_u32(smem);
    int tid = threadIdx.x, lane = tid & 31, wid = tid >> 5;

    if (wid < 8) {
        // ===================== PRODUCER =====================
        const float ninf = __int_as_float(0xff800000);
        uint32_t csum = (uint32_t)(lane >> 4) * 4096;       // ssum chunk (0 or 1)
        uint32_t cmax = csum + 2 * 4096;                    // smax chunk (2 or 3)
        uint32_t cb   = (uint32_t)(lane & 15) * 8;
        int r0 = wid * 4;                                    // 4 nodes per warp

        int it = 0;
        for (int tile = blockIdx.x; tile < NTILES; tile += GRIDSZ, it++) {
            int buf = it & 1;
            if (it >= 2) BAR_SYNC(3 + buf, THREADS);
            uint32_t abase_hi = sb + SA_BASE + buf * SA_BUFSZ;
            uint32_t abase_lo = abase_hi + 16384;

            int node0 = tile * TILE_M;
            int b = node0 >> 12;
            int nd0 = node0 & (NN - 1);
            const float* xb = xin + (size_t)b * NN * UU;
            const int* ep = ei + 2 * ((size_t)b * EE + (size_t)(nd0 + r0) * DEG);

            int myd[4];
            #pragma unroll
            for (int j = 0; j < 4; j++)
                myd[j] = (lane < DEG) ? ep[j * 2 * DEG + 2 * lane + 1] : 0;

            float4 s[4], mx[4];
            #pragma unroll
            for (int j = 0; j < 4; j++) {
                s[j] = make_float4(0.f, 0.f, 0.f, 0.f);
                mx[j] = make_float4(ninf, ninf, ninf, ninf);
            }
            #pragma unroll
            for (int e = 0; e < DEG; e++) {
                float4 v[4];
                #pragma unroll
                for (int j = 0; j < 4; j++) {
                    int d = __shfl_sync(0xffffffffu, myd[j], e);
                    v[j] = __ldg((const float4*)(xb + (size_t)d * UU + lane * 4));
                }
                #pragma unroll
                for (int j = 0; j < 4; j++) {
                    s[j].x += v[j].x; s[j].y += v[j].y; s[j].z += v[j].z; s[j].w += v[j].w;
                    mx[j].x = fmaxf(mx[j].x, v[j].x); mx[j].y = fmaxf(mx[j].y, v[j].y);
                    mx[j].z = fmaxf(mx[j].z, v[j].z); mx[j].w = fmaxf(mx[j].w, v[j].w);
                }
            }
            #pragma unroll
            for (int j = 0; j < 4; j++) {
                int r = r0 + j;
                float sv[4] = {s[j].x, s[j].y, s[j].z, s[j].w};
                float mv[4] = {mx[j].x, mx[j].y, mx[j].z, mx[j].w};
                uint32_t sh[4], sl[4], mh[4], ml[4];
                #pragma unroll
                for (int q = 0; q < 4; q++) {
                    __nv_bfloat16 h1 = __float2bfloat16_rn(sv[q]);
                    sh[q] = (uint32_t)__bfloat16_as_ushort(h1);
                    sl[q] = (uint32_t)__bfloat16_as_ushort(__float2bfloat16_rn(sv[q] - __bfloat162float(h1)));
                    __nv_bfloat16 h2 = __float2bfloat16_rn(mv[q]);
                    mh[q] = (uint32_t)__bfloat16_as_ushort(h2);
                    ml[q] = (uint32_t)__bfloat16_as_ushort(__float2bfloat16_rn(mv[q] - __bfloat162float(h2)));
                }
                uint32_t rowoff = (uint32_t)(r * 128) + (cb ^ (uint32_t)((r & 7) << 4));
                uint2 u;
                u.x = sh[0] | (sh[1] << 16); u.y = sh[2] | (sh[3] << 16);
                *(uint2*)((char*)smem + (abase_hi - sb) + csum + rowoff) = u;
                u.x = sl[0] | (sl[1] << 16); u.y = sl[2] | (sl[3] << 16);
                *(uint2*)((char*)smem + (abase_lo - sb) + csum + rowoff) = u;
                u.x = mh[0] | (mh[1] << 16); u.y = mh[2] | (mh[3] << 16);
                *(uint2*)((char*)smem + (abase_hi - sb) + cmax + rowoff) = u;
                u.x = ml[0] | (ml[1] << 16); u.y = ml[2] | (ml[3] << 16);
                *(uint2*)((char*)smem + (abase_lo - sb) + cmax + rowoff) = u;
            }
            BAR_ARRIVE(1 + buf, THREADS);
        }
    } else {
        // ===================== CONSUMER =====================
        int ctid = tid - 256;           // 0..255
        int wid_c = wid - 8;            // 0..7
        // stage B (hi+lo = 128KB) with consumer threads only
        const __nv_bfloat16* Bh = g_bhi + (size_t)l * UU * K2;
        const __nv_bfloat16* Bl = g_blo + (size_t)l * UU * K2;
        #pragma unroll
        for (int t = 0; t < 32; t++) {
            int q = ctid + t * 256;     // 0..8191
            int arr = q >> 12;
            int rem = q & 4095;
            int ch = rem >> 10;
            int seg = rem & 1023;
            int row = seg >> 3, sgi = seg & 7;
            uint32_t dst = sb + (arr ? SB_LO : SB_HI) + ch * 16384 + SWZ((uint32_t)(row * 128 + sgi * 16));
            const char* src = (const char*)(arr ? Bl : Bh) + (size_t)row * 512 + ch * 128 + sgi * 16;
            cp16(dst, src);
        }
        asm volatile("cp.async.commit_group;" ::: "memory");
        float* sepi = (float*)(smem + S_EPI);
        if (ctid < 128) {
            sepi[ctid]       = __ldg(bias + ctid);
            sepi[128 + ctid] = g_bn_a[l * UU + ctid];
            sepi[256 + ctid] = g_bn_d[l * UU + ctid];
        }
        asm volatile("cp.async.wait_group 0;" ::: "memory");
        BAR_SYNC(5, 256);   // consumer-only: B + epi visible to all consumer warps

        int warp_m = wid_c & 1, warp_n = wid_c >> 1;
        int rA = warp_m * 16 + (lane & 15);
        uint32_t kaA = (uint32_t)((lane >> 4) * 16);
        uint32_t a_off = (uint32_t)(rA * 128);
        uint32_t a_xor = (a_off >> 3) & 0x70;
        int lnB = (lane & 7) + ((lane >> 4) << 3);
        uint32_t kaB = (uint32_t)(((lane >> 3) & 1) * 16);
        uint32_t b_off[2], b_xor[2];
        #pragma unroll
        for (int p = 0; p < 2; p++) {
            int n = warp_n * 32 + p * 16 + lnB;
            b_off[p] = (uint32_t)(n * 128);
            b_xor[p] = (b_off[p] >> 3) & 0x70;
        }

        int it = 0;
        for (int tile = blockIdx.x; tile < NTILES; tile += GRIDSZ, it++) {
            int buf = it & 1;
            BAR_SYNC(1 + buf, THREADS);
            uint32_t abase_hi = sb + SA_BASE + buf * SA_BUFSZ;
            uint32_t abase_lo = abase_hi + 16384;

            float acc[4][4];
            #pragma unroll
            for (int j = 0; j < 4; j++)
                #pragma unroll
                for (int q = 0; q < 4; q++) acc[j][q] = 0.f;

            #pragma unroll
            for (int ch = 0; ch < 4; ch++) {
                uint32_t Ah  = abase_hi + ch * 4096;
                uint32_t Al  = abase_lo + ch * 4096;
                uint32_t Bhs = sb + SB_HI + ch * 16384;
                uint32_t Bls = sb + SB_LO + ch * 16384;
                #pragma unroll
                for (int ks = 0; ks < 4; ks++) {
                    uint32_t kb = (uint32_t)(ks * 32);
                    uint32_t ahi[4], alo[4], bhi[2][4], blo[2][4];
                    ldmx4(ahi, Ah + a_off + ((kb + kaA) ^ a_xor));
                    ldmx4(alo, Al + a_off + ((kb + kaA) ^ a_xor));
                    #pragma unroll
                    for (int p = 0; p < 2; p++) {
                        ldmx4(bhi[p], Bhs + b_off[p] + ((kb + kaB) ^ b_xor[p]));
                        ldmx4(blo[p], Bls + b_off[p] + ((kb + kaB) ^ b_xor[p]));
                    }
                    #pragma unroll
                    for (int j = 0; j < 4; j++) {
                        int p = j >> 1, s2 = (j & 1) * 2;
                        mma_bf16(acc[j], ahi, bhi[p][s2], bhi[p][s2 + 1]);
                        mma_bf16(acc[j], ahi, blo[p][s2], blo[p][s2 + 1]);
                        mma_bf16(acc[j], alo, bhi[p][s2], bhi[p][s2 + 1]);
                    }
                }
            }

            // epilogue
            int node0 = tile * TILE_M;
            int mbase = node0 + warp_m * 16 + (lane >> 2);
            #pragma unroll
            for (int j = 0; j < 4; j++) {
                int col = warp_n * 32 + j * 8 + (lane & 3) * 2;
                float b0 = sepi[col], b1 = sepi[col + 1];
                float a0 = sepi[128 + col], a1 = sepi[128 + col + 1];
                float d0 = sepi[256 + col], d1 = sepi[256 + col + 1];
                float2 o;
                o.x = fmaxf(acc[j][0] + b0, 0.f) * a0 + d0;
                o.y = fmaxf(acc[j][1] + b1, 0.f) * a1 + d1;
                *(float2*)&xout[(size_t)mbase * UU + col] = o;
                o.x = fmaxf(acc[j][2] + b0, 0.f) * a0 + d0;
                o.y = fmaxf(acc[j][3] + b1, 0.f) * a1 + d1;
                *(float2*)&xout[(size_t)(mbase + 8) * UU + col] = o;
            }
            BAR_ARRIVE(3 + buf, THREADS);
        }
    }
}

// ------------------- readout (parallel partial sums + atomicAdd) -------------------
__global__ void readout_kernel(const float* __restrict__ xin) {
    int b = blockIdx.x >> 4;
    int chunk = blockIdx.x & 15;
    int j = threadIdx.x;
    const float* xb = xin + (size_t)b * NN * UU + (size_t)chunk * 256 * UU;
    float s0 = 0.f, s1 = 0.f, s2 = 0.f, s3 = 0.f;
    for (int n = 0; n < 256; n += 4) {
        s0 += xb[(size_t)n * UU + j];
        s1 += xb[(size_t)(n + 1) * UU + j];
        s2 += xb[(size_t)(n + 2) * UU + j];
        s3 += xb[(size_t)(n + 3) * UU + j];
    }
    atomicAdd(&g_gm[b * UU + j], (s0 + s1 + s2 + s3) * (1.f / NN));
}

__global__ void mlp1_kernel(const float* __restrict__ Wp1, const float* __restrict__ bp1) {
    __shared__ float gs[UU];
    int b = blockIdx.x, j = threadIdx.x;
    gs[j] = g_gm[b * UU + j];
    __syncthreads();
    float acc = bp1[j];
    #pragma unroll 8
    for (int k = 0; k < UU; k++) acc += gs[k] * Wp1[k * UU + j];
    g_h1[b * UU + j] = fmaxf(acc, 0.f);
}

__global__ void mlp2_kernel(const float* __restrict__ Wp2, const float* __restrict__ bp2,
                            float* __restrict__ out) {
    __shared__ float gs[UU];
    int b = blockIdx.x, j = threadIdx.x;  // 64 threads
    gs[j] = g_h1[b * UU + j];
    gs[j + 64] = g_h1[b * UU + j + 64];
    __syncthreads();
    float acc = bp2[j];
    #pragma unroll 8
    for (int k = 0; k < UU; k++) acc += gs[k] * Wp2[k * 64 + j];
    out[b * 64 + j] = fmaxf(acc, 0.f);
}

// ------------------- launch -------------------
extern "C" void kernel_launch(void* const* d_in, const int* in_sizes, int n_in,
                              void* d_out, int out_size) {
    const float* x0    = (const float*)d_in[0];
    const int*   ei    = (const int*)d_in[1];
    const float* W     = (const float*)d_in[2];
    const float* bvec  = (const float*)d_in[3];
    const float* gamma = (const float*)d_in[4];
    const float* beta  = (const float*)d_in[5];
    const float* mmean = (const float*)d_in[6];
    const float* mvar  = (const float*)d_in[7];
    const float* Wp1   = (const float*)d_in[8];
    const float* bp1   = (const float*)d_in[9];
    const float* Wp2   = (const float*)d_in[10];
    const float* bp2   = (const float*)d_in[11];

    cudaFuncSetAttribute(fused_layer_kernel, cudaFuncAttributeMaxDynamicSharedMemorySize, FUSED_SMEM);

    fold_w_kernel<<<96, 1024>>>(W);
    fold_bn_kernel<<<3, 1024>>>(gamma, beta, mmean, mvar);

    float *xa, *xb;
    cudaGetSymbolAddress((void**)&xa, g_xa);
    cudaGetSymbolAddress((void**)&xb, g_xb);

    // l0: x0 -> xa,  l1: xa -> xb,  l2: xb -> xa
    fused_layer_kernel<<<GRIDSZ, THREADS, FUSED_SMEM>>>(0, x0, xa, ei, bvec + 0 * UU);
    fused_layer_kernel<<<GRIDSZ, THREADS, FUSED_SMEM>>>(1, xa, xb, ei, bvec + 1 * UU);
    fused_layer_kernel<<<GRIDSZ, THREADS, FUSED_SMEM>>>(2, xb, xa, ei, bvec + 2 * UU);

    readout_kernel<<<BB * 16, 128>>>(xa);
    mlp1_kernel<<<BB, 128>>>(Wp1, bp1);
    mlp2_kernel<<<BB, 64>>>(Wp2, bp2, (float*)d_out);
}

// round 9
// speedup vs baseline: 1.9582x; 1.0522x over previous
#include <cuda_runtime.h>
#include <cuda_bf16.h>
#include <math.h>
#include <stdint.h>

#define BB 8
#define NN 4096
#define DEG 16
#define UU 128
#define EE (NN*DEG)
#define MM (BB*NN)
#define K2 256
#define DEPTH 3
#define SCALE_C 1.2304489f
#define THREADS 768
#define TILE_M 32
#define NTILES (MM/TILE_M)
#define GRIDSZ 148

// ------------------- device scratch (ping-pong feature buffers) -------------------
__device__ float g_xa[(size_t)MM * UU];
__device__ float g_xb[(size_t)MM * UU];
__device__ __nv_bfloat16 g_bhi[DEPTH * UU * K2];       // folded W, [n][k] K-major, hi
__device__ __nv_bfloat16 g_blo[DEPTH * UU * K2];
__device__ float g_bn_a[DEPTH * UU];
__device__ float g_bn_d[DEPTH * UU];
__device__ float g_gm[BB * UU];
__device__ float g_h1[BB * UU];

// ------------------- helpers -------------------
__device__ __forceinline__ uint32_t smem_u32(const void* p) {
    uint32_t a;
    asm("{ .reg .u64 t; cvta.to.shared.u64 t, %1; cvt.u32.u64 %0, t; }" : "=r"(a) : "l"(p));
    return a;
}
__device__ __forceinline__ void cp16(uint32_t dst, const void* src) {
    asm volatile("cp.async.cg.shared.global [%0], [%1], 16;" :: "r"(dst), "l"(src) : "memory");
}
__device__ __forceinline__ void ldmx4(uint32_t* r, uint32_t addr) {
    asm volatile("ldmatrix.sync.aligned.m8n8.x4.shared.b16 {%0,%1,%2,%3}, [%4];"
                 : "=r"(r[0]), "=r"(r[1]), "=r"(r[2]), "=r"(r[3]) : "r"(addr));
}
__device__ __forceinline__ void mma_bf16(float* c, const uint32_t* a, uint32_t b0, uint32_t b1) {
    asm volatile("mma.sync.aligned.m16n8k16.row.col.f32.bf16.bf16.f32 "
                 "{%0,%1,%2,%3}, {%4,%5,%6,%7}, {%8,%9}, {%0,%1,%2,%3};"
                 : "+f"(c[0]), "+f"(c[1]), "+f"(c[2]), "+f"(c[3])
                 : "r"(a[0]), "r"(a[1]), "r"(a[2]), "r"(a[3]), "r"(b0), "r"(b1));
}
#define SWZ(off) ((off) ^ (((off) >> 3) & 0x70))
#define BAR_SYNC(id, cnt)   asm volatile("bar.sync %0, %1;"   :: "r"(id), "r"(cnt) : "memory")
#define BAR_ARRIVE(id, cnt) asm volatile("bar.arrive %0, %1;" :: "r"(id), "r"(cnt) : "memory")

// ------------------- weight folding (bf16 split, K-major [n][k]) -------------------
__global__ void fold_w_kernel(const float* __restrict__ W) {
    int t = blockIdx.x * blockDim.x + threadIdx.x;
    if (t >= DEPTH * K2 * UU) return;
    int j = t & 127;          // output feature n
    int k = (t >> 7) & 255;   // k index
    int l = t >> 15;
    const float c = SCALE_C;
    const float* Wl = W + (size_t)l * 1152 * UU;
    float v;
    if (k < 128) {
        float w0 = Wl[(0 * 128 + k) * UU + j];
        float w1 = Wl[(1 * 128 + k) * UU + j];
        float w2 = Wl[(2 * 128 + k) * UU + j];
        float w6 = Wl[(6 * 128 + k) * UU + j];
        float w7 = Wl[(7 * 128 + k) * UU + j];
        float w8 = Wl[(8 * 128 + k) * UU + j];
        v = (w0 + c * (w1 + w2)) * 0.0625f + w6 + c * (w7 + w8);
    } else {
        int kk = k - 128;
        float w3 = Wl[(3 * 128 + kk) * UU + j];
        float w4 = Wl[(4 * 128 + kk) * UU + j];
        float w5 = Wl[(5 * 128 + kk) * UU + j];
        v = w3 + c * (w4 + w5);
    }
    __nv_bfloat16 hi = __float2bfloat16_rn(v);
    size_t o = (size_t)l * UU * K2 + (size_t)j * K2 + k;
    g_bhi[o] = hi;
    g_blo[o] = __float2bfloat16_rn(v - __bfloat162float(hi));
}

// also zeroes g_gm for the readout accumulation
__global__ void fold_bn_kernel(const float* __restrict__ gamma, const float* __restrict__ beta,
                               const float* __restrict__ mm, const float* __restrict__ mv) {
    int t = blockIdx.x * blockDim.x + threadIdx.x;
    if (t < BB * UU) g_gm[t] = 0.f;
    if (t >= DEPTH * UU) return;
    float a = gamma[t] * rsqrtf(mv[t] + 1e-3f);
    g_bn_a[t] = a;
    g_bn_d[t] = beta[t] - mm[t] * a;
}

// ------------------- warp-specialized fused layer kernel -------------------
// 768 threads: warps 0-15 produce (gather->A smem, 2 nodes each, depth-2 prefetch),
// warps 16-23 consume (MMA+epilogue).
// Tile M=32, N=128, K=256. A double-buffered (2x32KB), B resident (128KB).
#define SB_HI   0
#define SB_LO   65536
#define SA_BASE 131072
#define SA_BUFSZ 32768
#define S_EPI   (131072 + 65536)
#define FUSED_SMEM (S_EPI + 3*128*4)
// named barriers: full[buf]=1+buf, empty[buf]=3+buf, consumer-init=5

__global__ __launch_bounds__(THREADS, 1) void fused_layer_kernel(
        int l, const float* __restrict__ xin, float* __restrict__ xout,
        const int* __restrict__ ei, const float* __restrict__ bias) {
    extern __shared__ __align__(1024) char smem[];
    uint32_t sb = smem_u32(smem);
    int tid = threadIdx.x, lane = tid & 31, wid = tid >> 5;

    if (wid < 16) {
        // ===================== PRODUCER (16 warps, 2 nodes each) =====================
        const float ninf = __int_as_float(0xff800000);
        uint32_t csum = (uint32_t)(lane >> 4) * 4096;       // ssum chunk (0 or 1)
        uint32_t cmax = csum + 2 * 4096;                    // smax chunk (2 or 3)
        uint32_t cb   = (uint32_t)(lane & 15) * 8;
        int r0 = wid * 2;                                    // 2 nodes per warp

        int it = 0;
        for (int tile = blockIdx.x; tile < NTILES; tile += GRIDSZ, it++) {
            int buf = it & 1;
            if (it >= 2) BAR_SYNC(3 + buf, THREADS);
            uint32_t abase_hi = sb + SA_BASE + buf * SA_BUFSZ;
            uint32_t abase_lo = abase_hi + 16384;

            int node0 = tile * TILE_M;
            int b = node0 >> 12;
            int nd0 = node0 & (NN - 1);
            const float* xb = xin + (size_t)b * NN * UU;
            const int* ep = ei + 2 * ((size_t)b * EE + (size_t)(nd0 + r0) * DEG);

            int myd0 = (lane < DEG) ? ep[2 * lane + 1] : 0;
            int myd1 = (lane < DEG) ? ep[2 * DEG + 2 * lane + 1] : 0;

            float4 s0 = make_float4(0.f, 0.f, 0.f, 0.f);
            float4 s1 = make_float4(0.f, 0.f, 0.f, 0.f);
            float4 m0 = make_float4(ninf, ninf, ninf, ninf);
            float4 m1 = make_float4(ninf, ninf, ninf, ninf);

            // depth-2 software prefetch
            float4 pf[2][2];
            #pragma unroll
            for (int pe = 0; pe < 2; pe++) {
                int d0 = __shfl_sync(0xffffffffu, myd0, pe);
                int d1 = __shfl_sync(0xffffffffu, myd1, pe);
                pf[pe][0] = __ldg((const float4*)(xb + (size_t)d0 * UU + lane * 4));
                pf[pe][1] = __ldg((const float4*)(xb + (size_t)d1 * UU + lane * 4));
            }
            #pragma unroll
            for (int e = 0; e < DEG; e++) {
                int nb = e & 1;
                float4 v0 = pf[nb][0];
                float4 v1 = pf[nb][1];
                if (e + 2 < DEG) {
                    int d0 = __shfl_sync(0xffffffffu, myd0, e + 2);
                    int d1 = __shfl_sync(0xffffffffu, myd1, e + 2);
                    pf[nb][0] = __ldg((const float4*)(xb + (size_t)d0 * UU + lane * 4));
                    pf[nb][1] = __ldg((const float4*)(xb + (size_t)d1 * UU + lane * 4));
                }
                s0.x += v0.x; s0.y += v0.y; s0.z += v0.z; s0.w += v0.w;
                m0.x = fmaxf(m0.x, v0.x); m0.y = fmaxf(m0.y, v0.y);
                m0.z = fmaxf(m0.z, v0.z); m0.w = fmaxf(m0.w, v0.w);
                s1.x += v1.x; s1.y += v1.y; s1.z += v1.z; s1.w += v1.w;
                m1.x = fmaxf(m1.x, v1.x); m1.y = fmaxf(m1.y, v1.y);
                m1.z = fmaxf(m1.z, v1.z); m1.w = fmaxf(m1.w, v1.w);
            }

            #pragma unroll
            for (int n2 = 0; n2 < 2; n2++) {
                int r = r0 + n2;
                float sv[4], mv[4];
                if (n2 == 0) { sv[0]=s0.x; sv[1]=s0.y; sv[2]=s0.z; sv[3]=s0.w;
                               mv[0]=m0.x; mv[1]=m0.y; mv[2]=m0.z; mv[3]=m0.w; }
                else         { sv[0]=s1.x; sv[1]=s1.y; sv[2]=s1.z; sv[3]=s1.w;
                               mv[0]=m1.x; mv[1]=m1.y; mv[2]=m1.z; mv[3]=m1.w; }
                uint32_t sh[4], sl[4], mh[4], ml[4];
                #pragma unroll
                for (int q = 0; q < 4; q++) {
                    __nv_bfloat16 h1 = __float2bfloat16_rn(sv[q]);
                    sh[q] = (uint32_t)__bfloat16_as_ushort(h1);
                    sl[q] = (uint32_t)__bfloat16_as_ushort(__float2bfloat16_rn(sv[q] - __bfloat162float(h1)));
                    __nv_bfloat16 h2 = __float2bfloat16_rn(mv[q]);
                    mh[q] = (uint32_t)__bfloat16_as_ushort(h2);
                    ml[q] = (uint32_t)__bfloat16_as_ushort(__float2bfloat16_rn(mv[q] - __bfloat162float(h2)));
                }
                uint32_t rowoff = (uint32_t)(r * 128) + (cb ^ (uint32_t)((r & 7) << 4));
                uint2 u;
                u.x = sh[0] | (sh[1] << 16); u.y = sh[2] | (sh[3] << 16);
                *(uint2*)((char*)smem + (abase_hi - sb) + csum + rowoff) = u;
                u.x = sl[0] | (sl[1] << 16); u.y = sl[2] | (sl[3] << 16);
                *(uint2*)((char*)smem + (abase_lo - sb) + csum + rowoff) = u;
                u.x = mh[0] | (mh[1] << 16); u.y = mh[2] | (mh[3] << 16);
                *(uint2*)((char*)smem + (abase_hi - sb) + cmax + rowoff) = u;
                u.x = ml[0] | (ml[1] << 16); u.y = ml[2] | (ml[3] << 16);
                *(uint2*)((char*)smem + (abase_lo - sb) + cmax + rowoff) = u;
            }
            BAR_ARRIVE(1 + buf, THREADS);
        }
    } else {
        // ===================== CONSUMER (warps 16-23) =====================
        int ctid = tid - 512;           // 0..255
        int wid_c = wid - 16;           // 0..7
        // stage B (hi+lo = 128KB) with consumer threads only
        const __nv_bfloat16* Bh = g_bhi + (size_t)l * UU * K2;
        const __nv_bfloat16* Bl = g_blo + (size_t)l * UU * K2;
        #pragma unroll
        for (int t = 0; t < 32; t++) {
            int q = ctid + t * 256;     // 0..8191
            int arr = q >> 12;
            int rem = q & 4095;
            int ch = rem >> 10;
            int seg = rem & 1023;
            int row = seg >> 3, sgi = seg & 7;
            uint32_t dst = sb + (arr ? SB_LO : SB_HI) + ch * 16384 + SWZ((uint32_t)(row * 128 + sgi * 16));
            const char* src = (const char*)(arr ? Bl : Bh) + (size_t)row * 512 + ch * 128 + sgi * 16;
            cp16(dst, src);
        }
        asm volatile("cp.async.commit_group;" ::: "memory");
        float* sepi = (float*)(smem + S_EPI);
        if (ctid < 128) {
            sepi[ctid]       = __ldg(bias + ctid);
            sepi[128 + ctid] = g_bn_a[l * UU + ctid];
            sepi[256 + ctid] = g_bn_d[l * UU + ctid];
        }
        asm volatile("cp.async.wait_group 0;" ::: "memory");
        BAR_SYNC(5, 256);   // consumer-only: B + epi visible to all consumer warps

        int warp_m = wid_c & 1, warp_n = wid_c >> 1;
        int rA = warp_m * 16 + (lane & 15);
        uint32_t kaA = (uint32_t)((lane >> 4) * 16);
        uint32_t a_off = (uint32_t)(rA * 128);
        uint32_t a_xor = (a_off >> 3) & 0x70;
        int lnB = (lane & 7) + ((lane >> 4) << 3);
        uint32_t kaB = (uint32_t)(((lane >> 3) & 1) * 16);
        uint32_t b_off[2], b_xor[2];
        #pragma unroll
        for (int p = 0; p < 2; p++) {
            int n = warp_n * 32 + p * 16 + lnB;
            b_off[p] = (uint32_t)(n * 128);
            b_xor[p] = (b_off[p] >> 3) & 0x70;
        }

        int it = 0;
        for (int tile = blockIdx.x; tile < NTILES; tile += GRIDSZ, it++) {
            int buf = it & 1;
            BAR_SYNC(1 + buf, THREADS);
            uint32_t abase_hi = sb + SA_BASE + buf * SA_BUFSZ;
            uint32_t abase_lo = abase_hi + 16384;

            float acc[4][4];
            #pragma unroll
            for (int j = 0; j < 4; j++)
                #pragma unroll
                for (int q = 0; q < 4; q++) acc[j][q] = 0.f;

            #pragma unroll
            for (int ch = 0; ch < 4; ch++) {
                uint32_t Ah  = abase_hi + ch * 4096;
                uint32_t Al  = abase_lo + ch * 4096;
                uint32_t Bhs = sb + SB_HI + ch * 16384;
                uint32_t Bls = sb + SB_LO + ch * 16384;
                #pragma unroll
                for (int ks = 0; ks < 4; ks++) {
                    uint32_t kb = (uint32_t)(ks * 32);
                    uint32_t ahi[4], alo[4], bhi[2][4], blo[2][4];
                    ldmx4(ahi, Ah + a_off + ((kb + kaA) ^ a_xor));
                    ldmx4(alo, Al + a_off + ((kb + kaA) ^ a_xor));
                    #pragma unroll
                    for (int p = 0; p < 2; p++) {
                        ldmx4(bhi[p], Bhs + b_off[p] + ((kb + kaB) ^ b_xor[p]));
                        ldmx4(blo[p], Bls + b_off[p] + ((kb + kaB) ^ b_xor[p]));
                    }
                    #pragma unroll
                    for (int j = 0; j < 4; j++) {
                        int p = j >> 1, s2 = (j & 1) * 2;
                        mma_bf16(acc[j], ahi, bhi[p][s2], bhi[p][s2 + 1]);
                        mma_bf16(acc[j], ahi, blo[p][s2], blo[p][s2 + 1]);
                        mma_bf16(acc[j], alo, bhi[p][s2], bhi[p][s2 + 1]);
                    }
                }
            }

            // epilogue
            int node0 = tile * TILE_M;
            int mbase = node0 + warp_m * 16 + (lane >> 2);
            #pragma unroll
            for (int j = 0; j < 4; j++) {
                int col = warp_n * 32 + j * 8 + (lane & 3) * 2;
                float b0 = sepi[col], b1 = sepi[col + 1];
                float a0 = sepi[128 + col], a1 = sepi[128 + col + 1];
                float d0 = sepi[256 + col], d1 = sepi[256 + col + 1];
                float2 o;
                o.x = fmaxf(acc[j][0] + b0, 0.f) * a0 + d0;
                o.y = fmaxf(acc[j][1] + b1, 0.f) * a1 + d1;
                *(float2*)&xout[(size_t)mbase * UU + col] = o;
                o.x = fmaxf(acc[j][2] + b0, 0.f) * a0 + d0;
                o.y = fmaxf(acc[j][3] + b1, 0.f) * a1 + d1;
                *(float2*)&xout[(size_t)(mbase + 8) * UU + col] = o;
            }
            BAR_ARRIVE(3 + buf, THREADS);
        }
    }
}

// ------------------- readout (parallel partial sums + atomicAdd) -------------------
__global__ void readout_kernel(const float* __restrict__ xin) {
    int b = blockIdx.x >> 4;
    int chunk = blockIdx.x & 15;
    int j = threadIdx.x;
    const float* xb = xin + (size_t)b * NN * UU + (size_t)chunk * 256 * UU;
    float s0 = 0.f, s1 = 0.f, s2 = 0.f, s3 = 0.f;
    for (int n = 0; n < 256; n += 4) {
        s0 += xb[(size_t)n * UU + j];
        s1 += xb[(size_t)(n + 1) * UU + j];
        s2 += xb[(size_t)(n + 2) * UU + j];
        s3 += xb[(size_t)(n + 3) * UU + j];
    }
    atomicAdd(&g_gm[b * UU + j], (s0 + s1 + s2 + s3) * (1.f / NN));
}

__global__ void mlp1_kernel(const float* __restrict__ Wp1, const float* __restrict__ bp1) {
    __shared__ float gs[UU];
    int b = blockIdx.x, j = threadIdx.x;
    gs[j] = g_gm[b * UU + j];
    __syncthreads();
    float acc = bp1[j];
    #pragma unroll 8
    for (int k = 0; k < UU; k++) acc += gs[k] * Wp1[k * UU + j];
    g_h1[b * UU + j] = fmaxf(acc, 0.f);
}

__global__ void mlp2_kernel(const float* __restrict__ Wp2, const float* __restrict__ bp2,
                            float* __restrict__ out) {
    __shared__ float gs[UU];
    int b = blockIdx.x, j = threadIdx.x;  // 64 threads
    gs[j] = g_h1[b * UU + j];
    gs[j + 64] = g_h1[b * UU + j + 64];
    __syncthreads();
    float acc = bp2[j];
    #pragma unroll 8
    for (int k = 0; k < UU; k++) acc += gs[k] * Wp2[k * 64 + j];
    out[b * 64 + j] = fmaxf(acc, 0.f);
}

// ------------------- launch -------------------
extern "C" void kernel_launch(void* const* d_in, const int* in_sizes, int n_in,
                              void* d_out, int out_size) {
    const float* x0    = (const float*)d_in[0];
    const int*   ei    = (const int*)d_in[1];
    const float* W     = (const float*)d_in[2];
    const float* bvec  = (const float*)d_in[3];
    const float* gamma = (const float*)d_in[4];
    const float* beta  = (const float*)d_in[5];
    const float* mmean = (const float*)d_in[6];
    const float* mvar  = (const float*)d_in[7];
    const float* Wp1   = (const float*)d_in[8];
    const float* bp1   = (const float*)d_in[9];
    const float* Wp2   = (const float*)d_in[10];
    const float* bp2   = (const float*)d_in[11];

    cudaFuncSetAttribute(fused_layer_kernel, cudaFuncAttributeMaxDynamicSharedMemorySize, FUSED_SMEM);

    fold_w_kernel<<<96, 1024>>>(W);
    fold_bn_kernel<<<3, 1024>>>(gamma, beta, mmean, mvar);

    float *xa, *xb;
    cudaGetSymbolAddress((void**)&xa, g_xa);
    cudaGetSymbolAddress((void**)&xb, g_xb);

    // l0: x0 -> xa,  l1: xa -> xb,  l2: xb -> xa
    fused_layer_kernel<<<GRIDSZ, THREADS, FUSED_SMEM>>>(0, x0, xa, ei, bvec + 0 * UU);
    fused_layer_kernel<<<GRIDSZ, THREADS, FUSED_SMEM>>>(1, xa, xb, ei, bvec + 1 * UU);
    fused_layer_kernel<<<GRIDSZ, THREADS, FUSED_SMEM>>>(2, xb, xa, ei, bvec + 2 * UU);

    readout_kernel<<<BB * 16, 128>>>(xa);
    mlp1_kernel<<<BB, 128>>>(Wp1, bp1);
    mlp2_kernel<<<BB, 64>>>(Wp2, bp2, (float*)d_out);
}

// round 10
// speedup vs baseline: 2.2005x; 1.1237x over previous
#include <cuda_runtime.h>
#include <cuda_bf16.h>
#include <math.h>
#include <stdint.h>

#define BB 8
#define NN 4096
#define DEG 16
#define UU 128
#define EE (NN*DEG)
#define MM (BB*NN)
#define K2 256
#define DEPTH 3
#define SCALE_C 1.2304489f
#define THREADS 640
#define TILE_M 32
#define NTILES (MM/TILE_M)
#define GRIDSZ 148

// ------------------- device scratch (ping-pong feature buffers) -------------------
__device__ float g_xa[(size_t)MM * UU];
__device__ float g_xb[(size_t)MM * UU];
__device__ __nv_bfloat16 g_bhi[DEPTH * UU * K2];       // folded W, [n][k] K-major, hi
__device__ __nv_bfloat16 g_blo[DEPTH * UU * K2];
__device__ float g_bn_a[DEPTH * UU];
__device__ float g_bn_d[DEPTH * UU];
__device__ float g_gm[BB * UU];
__device__ float g_h1[BB * UU];

// ------------------- helpers -------------------
__device__ __forceinline__ uint32_t smem_u32(const void* p) {
    uint32_t a;
    asm("{ .reg .u64 t; cvta.to.shared.u64 t, %1; cvt.u32.u64 %0, t; }" : "=r"(a) : "l"(p));
    return a;
}
__device__ __forceinline__ void cp16(uint32_t dst, const void* src) {
    asm volatile("cp.async.cg.shared.global [%0], [%1], 16;" :: "r"(dst), "l"(src) : "memory");
}
__device__ __forceinline__ void ldmx4(uint32_t* r, uint32_t addr) {
    asm volatile("ldmatrix.sync.aligned.m8n8.x4.shared.b16 {%0,%1,%2,%3}, [%4];"
                 : "=r"(r[0]), "=r"(r[1]), "=r"(r[2]), "=r"(r[3]) : "r"(addr));
}
__device__ __forceinline__ void mma_bf16(float* c, const uint32_t* a, uint32_t b0, uint32_t b1) {
    asm volatile("mma.sync.aligned.m16n8k16.row.col.f32.bf16.bf16.f32 "
                 "{%0,%1,%2,%3}, {%4,%5,%6,%7}, {%8,%9}, {%0,%1,%2,%3};"
                 : "+f"(c[0]), "+f"(c[1]), "+f"(c[2]), "+f"(c[3])
                 : "r"(a[0]), "r"(a[1]), "r"(a[2]), "r"(a[3]), "r"(b0), "r"(b1));
}
#define SWZ(off) ((off) ^ (((off) >> 3) & 0x70))
#define BAR_SYNC(id, cnt)   asm volatile("bar.sync %0, %1;"   :: "r"(id), "r"(cnt) : "memory")
#define BAR_ARRIVE(id, cnt) asm volatile("bar.arrive %0, %1;" :: "r"(id), "r"(cnt) : "memory")

// ------------------- weight folding (bf16 split, K-major [n][k]) -------------------
__global__ void fold_w_kernel(const float* __restrict__ W) {
    int t = blockIdx.x * blockDim.x + threadIdx.x;
    if (t >= DEPTH * K2 * UU) return;
    int j = t & 127;          // output feature n
    int k = (t >> 7) & 255;   // k index
    int l = t >> 15;
    const float c = SCALE_C;
    const float* Wl = W + (size_t)l * 1152 * UU;
    float v;
    if (k < 128) {
        float w0 = Wl[(0 * 128 + k) * UU + j];
        float w1 = Wl[(1 * 128 + k) * UU + j];
        float w2 = Wl[(2 * 128 + k) * UU + j];
        float w6 = Wl[(6 * 128 + k) * UU + j];
        float w7 = Wl[(7 * 128 + k) * UU + j];
        float w8 = Wl[(8 * 128 + k) * UU + j];
        v = (w0 + c * (w1 + w2)) * 0.0625f + w6 + c * (w7 + w8);
    } else {
        int kk = k - 128;
        float w3 = Wl[(3 * 128 + kk) * UU + j];
        float w4 = Wl[(4 * 128 + kk) * UU + j];
        float w5 = Wl[(5 * 128 + kk) * UU + j];
        v = w3 + c * (w4 + w5);
    }
    __nv_bfloat16 hi = __float2bfloat16_rn(v);
    size_t o = (size_t)l * UU * K2 + (size_t)j * K2 + k;
    g_bhi[o] = hi;
    g_blo[o] = __float2bfloat16_rn(v - __bfloat162float(hi));
}

// also zeroes g_gm for the fused readout accumulation
__global__ void fold_bn_kernel(const float* __restrict__ gamma, const float* __restrict__ beta,
                               const float* __restrict__ mm, const float* __restrict__ mv) {
    int t = blockIdx.x * blockDim.x + threadIdx.x;
    if (t < BB * UU) g_gm[t] = 0.f;
    if (t >= DEPTH * UU) return;
    float a = gamma[t] * rsqrtf(mv[t] + 1e-3f);
    g_bn_a[t] = a;
    g_bn_d[t] = beta[t] - mm[t] * a;
}

// ------------------- warp-specialized fused layer kernel -------------------
// 640 threads: warps 0-15 produce (gather->A smem, 2 nodes each, depth-2 prefetch),
// warps 16-19 consume (MMA M=32 full x N=32 slice each + epilogue).
// Tile M=32, N=128, K=256. A double-buffered (2x32KB), B resident (128KB).
// If fuse_readout, layer output is column-reduced and atomicAdd'ed to g_gm
// instead of being written to xout.
#define SB_HI   0
#define SB_LO   65536
#define SA_BASE 131072
#define SA_BUFSZ 32768
#define S_EPI   (131072 + 65536)
#define FUSED_SMEM (S_EPI + 3*128*4)
// named barriers: full[buf]=1+buf, empty[buf]=3+buf, consumer-init=5

__global__ __launch_bounds__(THREADS, 1) void fused_layer_kernel(
        int l, const float* __restrict__ xin, float* __restrict__ xout,
        const int* __restrict__ ei, const float* __restrict__ bias,
        int fuse_readout) {
    extern __shared__ __align__(1024) char smem[];
    uint32_t sb = smem_u32(smem);
    int tid = threadIdx.x, lane = tid & 31, wid = tid >> 5;

    if (wid < 16) {
        // ===================== PRODUCER (16 warps, 2 nodes each) =====================
        const float ninf = __int_as_float(0xff800000);
        uint32_t csum = (uint32_t)(lane >> 4) * 4096;       // ssum chunk (0 or 1)
        uint32_t cmax = csum + 2 * 4096;                    // smax chunk (2 or 3)
        uint32_t cb   = (uint32_t)(lane & 15) * 8;
        int r0 = wid * 2;                                    // 2 nodes per warp

        int it = 0;
        for (int tile = blockIdx.x; tile < NTILES; tile += GRIDSZ, it++) {
            int buf = it & 1;
            if (it >= 2) BAR_SYNC(3 + buf, THREADS);
            uint32_t abase_hi = sb + SA_BASE + buf * SA_BUFSZ;
            uint32_t abase_lo = abase_hi + 16384;

            int node0 = tile * TILE_M;
            int b = node0 >> 12;
            int nd0 = node0 & (NN - 1);
            const float* xb = xin + (size_t)b * NN * UU;
            const int* ep = ei + 2 * ((size_t)b * EE + (size_t)(nd0 + r0) * DEG);

            int myd0 = (lane < DEG) ? ep[2 * lane + 1] : 0;
            int myd1 = (lane < DEG) ? ep[2 * DEG + 2 * lane + 1] : 0;

            float4 s0 = make_float4(0.f, 0.f, 0.f, 0.f);
            float4 s1 = make_float4(0.f, 0.f, 0.f, 0.f);
            float4 m0 = make_float4(ninf, ninf, ninf, ninf);
            float4 m1 = make_float4(ninf, ninf, ninf, ninf);

            // depth-2 software prefetch
            float4 pf[2][2];
            #pragma unroll
            for (int pe = 0; pe < 2; pe++) {
                int d0 = __shfl_sync(0xffffffffu, myd0, pe);
                int d1 = __shfl_sync(0xffffffffu, myd1, pe);
                pf[pe][0] = __ldg((const float4*)(xb + (size_t)d0 * UU + lane * 4));
                pf[pe][1] = __ldg((const float4*)(xb + (size_t)d1 * UU + lane * 4));
            }
            #pragma unroll
            for (int e = 0; e < DEG; e++) {
                int nb = e & 1;
                float4 v0 = pf[nb][0];
                float4 v1 = pf[nb][1];
                if (e + 2 < DEG) {
                    int d0 = __shfl_sync(0xffffffffu, myd0, e + 2);
                    int d1 = __shfl_sync(0xffffffffu, myd1, e + 2);
                    pf[nb][0] = __ldg((const float4*)(xb + (size_t)d0 * UU + lane * 4));
                    pf[nb][1] = __ldg((const float4*)(xb + (size_t)d1 * UU + lane * 4));
                }
                s0.x += v0.x; s0.y += v0.y; s0.z += v0.z; s0.w += v0.w;
                m0.x = fmaxf(m0.x, v0.x); m0.y = fmaxf(m0.y, v0.y);
                m0.z = fmaxf(m0.z, v0.z); m0.w = fmaxf(m0.w, v0.w);
                s1.x += v1.x; s1.y += v1.y; s1.z += v1.z; s1.w += v1.w;
                m1.x = fmaxf(m1.x, v1.x); m1.y = fmaxf(m1.y, v1.y);
                m1.z = fmaxf(m1.z, v1.z); m1.w = fmaxf(m1.w, v1.w);
            }

            #pragma unroll
            for (int n2 = 0; n2 < 2; n2++) {
                int r = r0 + n2;
                float sv[4], mv[4];
                if (n2 == 0) { sv[0]=s0.x; sv[1]=s0.y; sv[2]=s0.z; sv[3]=s0.w;
                               mv[0]=m0.x; mv[1]=m0.y; mv[2]=m0.z; mv[3]=m0.w; }
                else         { sv[0]=s1.x; sv[1]=s1.y; sv[2]=s1.z; sv[3]=s1.w;
                               mv[0]=m1.x; mv[1]=m1.y; mv[2]=m1.z; mv[3]=m1.w; }
                uint32_t sh[4], sl[4], mh[4], ml[4];
                #pragma unroll
                for (int q = 0; q < 4; q++) {
                    __nv_bfloat16 h1 = __float2bfloat16_rn(sv[q]);
                    sh[q] = (uint32_t)__bfloat16_as_ushort(h1);
                    sl[q] = (uint32_t)__bfloat16_as_ushort(__float2bfloat16_rn(sv[q] - __bfloat162float(h1)));
                    __nv_bfloat16 h2 = __float2bfloat16_rn(mv[q]);
                    mh[q] = (uint32_t)__bfloat16_as_ushort(h2);
                    ml[q] = (uint32_t)__bfloat16_as_ushort(__float2bfloat16_rn(mv[q] - __bfloat162float(h2)));
                }
                uint32_t rowoff = (uint32_t)(r * 128) + (cb ^ (uint32_t)((r & 7) << 4));
                uint2 u;
                u.x = sh[0] | (sh[1] << 16); u.y = sh[2] | (sh[3] << 16);
                *(uint2*)((char*)smem + (abase_hi - sb) + csum + rowoff) = u;
                u.x = sl[0] | (sl[1] << 16); u.y = sl[2] | (sl[3] << 16);
                *(uint2*)((char*)smem + (abase_lo - sb) + csum + rowoff) = u;
                u.x = mh[0] | (mh[1] << 16); u.y = mh[2] | (mh[3] << 16);
                *(uint2*)((char*)smem + (abase_hi - sb) + cmax + rowoff) = u;
                u.x = ml[0] | (ml[1] << 16); u.y = ml[2] | (ml[3] << 16);
                *(uint2*)((char*)smem + (abase_lo - sb) + cmax + rowoff) = u;
            }
            BAR_ARRIVE(1 + buf, THREADS);
        }
    } else {
        // ===================== CONSUMER (warps 16-19) =====================
        int ctid = tid - 512;           // 0..127
        int warp_n = wid - 16;          // 0..3, N=32 slice each; M=32 full
        // stage B (hi+lo = 128KB) with consumer threads only
        const __nv_bfloat16* Bh = g_bhi + (size_t)l * UU * K2;
        const __nv_bfloat16* Bl = g_blo + (size_t)l * UU * K2;
        #pragma unroll
        for (int t = 0; t < 64; t++) {
            int q = ctid + t * 128;     // 0..8191
            int arr = q >> 12;
            int rem = q & 4095;
            int ch = rem >> 10;
            int seg = rem & 1023;
            int row = seg >> 3, sgi = seg & 7;
            uint32_t dst = sb + (arr ? SB_LO : SB_HI) + ch * 16384 + SWZ((uint32_t)(row * 128 + sgi * 16));
            const char* src = (const char*)(arr ? Bl : Bh) + (size_t)row * 512 + ch * 128 + sgi * 16;
            cp16(dst, src);
        }
        asm volatile("cp.async.commit_group;" ::: "memory");
        float* sepi = (float*)(smem + S_EPI);
        if (ctid < 128) {
            sepi[ctid]       = __ldg(bias + ctid);
            sepi[128 + ctid] = g_bn_a[l * UU + ctid];
            sepi[256 + ctid] = g_bn_d[l * UU + ctid];
        }
        asm volatile("cp.async.wait_group 0;" ::: "memory");
        BAR_SYNC(5, 128);   // consumer-only: B + epi visible to all consumer warps

        uint32_t kaA = (uint32_t)((lane >> 4) * 16);
        uint32_t a_off[2], a_xor[2];
        #pragma unroll
        for (int i = 0; i < 2; i++) {
            int r = i * 16 + (lane & 15);
            a_off[i] = (uint32_t)(r * 128);
            a_xor[i] = (a_off[i] >> 3) & 0x70;
        }
        int lnB = (lane & 7) + ((lane >> 4) << 3);
        uint32_t kaB = (uint32_t)(((lane >> 3) & 1) * 16);
        uint32_t b_off[2], b_xor[2];
        #pragma unroll
        for (int p = 0; p < 2; p++) {
            int n = warp_n * 32 + p * 16 + lnB;
            b_off[p] = (uint32_t)(n * 128);
            b_xor[p] = (b_off[p] >> 3) & 0x70;
        }

        int it = 0;
        for (int tile = blockIdx.x; tile < NTILES; tile += GRIDSZ, it++) {
            int buf = it & 1;
            BAR_SYNC(1 + buf, THREADS);
            uint32_t abase_hi = sb + SA_BASE + buf * SA_BUFSZ;
            uint32_t abase_lo = abase_hi + 16384;

            float acc[2][4][4];
            #pragma unroll
            for (int i = 0; i < 2; i++)
                #pragma unroll
                for (int j = 0; j < 4; j++)
                    #pragma unroll
                    for (int q = 0; q < 4; q++) acc[i][j][q] = 0.f;

            #pragma unroll
            for (int ch = 0; ch < 4; ch++) {
                uint32_t Ah  = abase_hi + ch * 4096;
                uint32_t Al  = abase_lo + ch * 4096;
                uint32_t Bhs = sb + SB_HI + ch * 16384;
                uint32_t Bls = sb + SB_LO + ch * 16384;
                #pragma unroll
                for (int ks = 0; ks < 4; ks++) {
                    uint32_t kb = (uint32_t)(ks * 32);
                    uint32_t ahi[2][4], alo[2][4], bhi[2][4], blo[2][4];
                    #pragma unroll
                    for (int i = 0; i < 2; i++) {
                        ldmx4(ahi[i], Ah + a_off[i] + ((kb + kaA) ^ a_xor[i]));
                        ldmx4(alo[i], Al + a_off[i] + ((kb + kaA) ^ a_xor[i]));
                    }
                    #pragma unroll
                    for (int p = 0; p < 2; p++) {
                        ldmx4(bhi[p], Bhs + b_off[p] + ((kb + kaB) ^ b_xor[p]));
                        ldmx4(blo[p], Bls + b_off[p] + ((kb + kaB) ^ b_xor[p]));
                    }
                    #pragma unroll
                    for (int i = 0; i < 2; i++)
                        #pragma unroll
                        for (int j = 0; j < 4; j++) {
                            int p = j >> 1, s2 = (j & 1) * 2;
                            mma_bf16(acc[i][j], ahi[i], bhi[p][s2], bhi[p][s2 + 1]);
                            mma_bf16(acc[i][j], ahi[i], blo[p][s2], blo[p][s2 + 1]);
                            mma_bf16(acc[i][j], alo[i], bhi[p][s2], bhi[p][s2 + 1]);
                        }
                }
            }

            // ---- epilogue ----
            int node0 = tile * TILE_M;
            if (!fuse_readout) {
                int mbase = node0 + (lane >> 2);
                #pragma unroll
                for (int i = 0; i < 2; i++)
                    #pragma unroll
                    for (int j = 0; j < 4; j++) {
                        int col = warp_n * 32 + j * 8 + (lane & 3) * 2;
                        float b0 = sepi[col], b1 = sepi[col + 1];
                        float a0 = sepi[128 + col], a1 = sepi[128 + col + 1];
                        float d0 = sepi[256 + col], d1 = sepi[256 + col + 1];
                        int r0 = mbase + i * 16;
                        float2 o;
                        o.x = fmaxf(acc[i][j][0] + b0, 0.f) * a0 + d0;
                        o.y = fmaxf(acc[i][j][1] + b1, 0.f) * a1 + d1;
                        *(float2*)&xout[(size_t)r0 * UU + col] = o;
                        o.x = fmaxf(acc[i][j][2] + b0, 0.f) * a0 + d0;
                        o.y = fmaxf(acc[i][j][3] + b1, 0.f) * a1 + d1;
                        *(float2*)&xout[(size_t)(r0 + 8) * UU + col] = o;
                    }
            } else {
                // final layer: column-reduce post-BN values and atomicAdd to g_gm
                int b = node0 >> 12;
                float cs0[4], cs1[4];
                #pragma unroll
                for (int j = 0; j < 4; j++) { cs0[j] = 0.f; cs1[j] = 0.f; }
                #pragma unroll
                for (int i = 0; i < 2; i++)
                    #pragma unroll
                    for (int j = 0; j < 4; j++) {
                        int col = warp_n * 32 + j * 8 + (lane & 3) * 2;
                        float b0 = sepi[col], b1 = sepi[col + 1];
                        float a0 = sepi[128 + col], a1 = sepi[128 + col + 1];
                        float d0 = sepi[256 + col], d1 = sepi[256 + col + 1];
                        cs0[j] += fmaxf(acc[i][j][0] + b0, 0.f) * a0 + d0
                                + fmaxf(acc[i][j][2] + b0, 0.f) * a0 + d0;
                        cs1[j] += fmaxf(acc[i][j][1] + b1, 0.f) * a1 + d1
                                + fmaxf(acc[i][j][3] + b1, 0.f) * a1 + d1;
                    }
                #pragma unroll
                for (int j = 0; j < 4; j++) {
                    #pragma unroll
                    for (int e = 4; e < 32; e <<= 1) {
                        cs0[j] += __shfl_xor_sync(0xffffffffu, cs0[j], e);
                        cs1[j] += __shfl_xor_sync(0xffffffffu, cs1[j], e);
                    }
                }
                if (lane < 4) {
                    #pragma unroll
                    for (int j = 0; j < 4; j++) {
                        int col = warp_n * 32 + j * 8 + lane * 2;
                        atomicAdd(&g_gm[b * UU + col],     cs0[j] * (1.f / NN));
                        atomicAdd(&g_gm[b * UU + col + 1], cs1[j] * (1.f / NN));
                    }
                }
            }
            BAR_ARRIVE(3 + buf, THREADS);
        }
    }
}

__global__ void mlp1_kernel(const float* __restrict__ Wp1, const float* __restrict__ bp1) {
    __shared__ float gs[UU];
    int b = blockIdx.x, j = threadIdx.x;
    gs[j] = g_gm[b * UU + j];
    __syncthreads();
    float acc = bp1[j];
    #pragma unroll 8
    for (int k = 0; k < UU; k++) acc += gs[k] * Wp1[k * UU + j];
    g_h1[b * UU + j] = fmaxf(acc, 0.f);
}

__global__ void mlp2_kernel(const float* __restrict__ Wp2, const float* __restrict__ bp2,
                            float* __restrict__ out) {
    __shared__ float gs[UU];
    int b = blockIdx.x, j = threadIdx.x;  // 64 threads
    gs[j] = g_h1[b * UU + j];
    gs[j + 64] = g_h1[b * UU + j + 64];
    __syncthreads();
    float acc = bp2[j];
    #pragma unroll 8
    for (int k = 0; k < UU; k++) acc += gs[k] * Wp2[k * 64 + j];
    out[b * 64 + j] = fmaxf(acc, 0.f);
}

// ------------------- launch -------------------
extern "C" void kernel_launch(void* const* d_in, const int* in_sizes, int n_in,
                              void* d_out, int out_size) {
    const float* x0    = (const float*)d_in[0];
    const int*   ei    = (const int*)d_in[1];
    const float* W     = (const float*)d_in[2];
    const float* bvec  = (const float*)d_in[3];
    const float* gamma = (const float*)d_in[4];
    const float* beta  = (const float*)d_in[5];
    const float* mmean = (const float*)d_in[6];
    const float* mvar  = (const float*)d_in[7];
    const float* Wp1   = (const float*)d_in[8];
    const float* bp1   = (const float*)d_in[9];
    const float* Wp2   = (const float*)d_in[10];
    const float* bp2   = (const float*)d_in[11];

    cudaFuncSetAttribute(fused_layer_kernel, cudaFuncAttributeMaxDynamicSharedMemorySize, FUSED_SMEM);

    fold_w_kernel<<<96, 1024>>>(W);
    fold_bn_kernel<<<3, 1024>>>(gamma, beta, mmean, mvar);

    float *xa, *xb;
    cudaGetSymbolAddress((void**)&xa, g_xa);
    cudaGetSymbolAddress((void**)&xb, g_xb);

    // l0: x0 -> xa,  l1: xa -> xb,  l2: xb -> (fused readout into g_gm)
    fused_layer_kernel<<<GRIDSZ, THREADS, FUSED_SMEM>>>(0, x0, xa, ei, bvec + 0 * UU, 0);
    fused_layer_kernel<<<GRIDSZ, THREADS, FUSED_SMEM>>>(1, xa, xb, ei, bvec + 1 * UU, 0);
    fused_layer_kernel<<<GRIDSZ, THREADS, FUSED_SMEM>>>(2, xb, xa, ei, bvec + 2 * UU, 1);

    mlp1_kernel<<<BB, 128>>>(Wp1, bp1);
    mlp2_kernel<<<BB, 64>>>(Wp2, bp2, (float*)d_out);
}